// round 2
// baseline (speedup 1.0000x reference)
#include <cuda_runtime.h>
#include <cstdint>

// RelationProbe: out[r*B + i] = dot(z[i,:], W[r, pair_idx[i], :]) + b[r, pair_idx[i]]
// B = 4194304, D = 64, 4 relations, 6 pairs.
//
// HBM-bound streaming design:
//  - warp-cooperative coalesced global loads of z into an XOR-swizzled SMEM tile
//  - thread-per-row dot against W packed in SMEM as float4(W[0..3][p][d]) with
//    stride 65 so distinct pairs hit distinct bank octants
//  - pair_idx read as int32 (JAX canonicalizes int64->int32 by default)

#define ROWS_PER_BLOCK 256
#define WARPS_PER_BLOCK 8

__global__ void __launch_bounds__(256, 1)
relation_probe_kernel(const float4* __restrict__ z4,
                      const float* __restrict__ Wg,     // [4][6][64]
                      const float* __restrict__ bg,     // [4][6]
                      const int* __restrict__ pidx,     // [B] int32
                      float* __restrict__ out,          // [4][B]
                      int B)
{
    __shared__ float4 Ws[6 * 65];
    __shared__ float4 biass[6];
    __shared__ float4 zs[WARPS_PER_BLOCK][256];

    const int tid = threadIdx.x;

    // --- Stage W + bias into shared (once per block) ---
    for (int t = tid; t < 6 * 64; t += 256) {
        int p = t >> 6;
        int d = t & 63;
        Ws[p * 65 + d] = make_float4(Wg[(0 * 6 + p) * 64 + d],
                                     Wg[(1 * 6 + p) * 64 + d],
                                     Wg[(2 * 6 + p) * 64 + d],
                                     Wg[(3 * 6 + p) * 64 + d]);
    }
    if (tid < 6) {
        biass[tid] = make_float4(bg[0 * 6 + tid], bg[1 * 6 + tid],
                                 bg[2 * 6 + tid], bg[3 * 6 + tid]);
    }
    __syncthreads();

    const int warp = tid >> 5;
    const int lane = tid & 31;
    const int rowBase = blockIdx.x * ROWS_PER_BLOCK + warp * 32;
    const int row = rowBase + lane;

    const int p = pidx[row];                // 0..5
    const float4* __restrict__ wrow = &Ws[p * 65];
    float4 acc = biass[p];

    #pragma unroll
    for (int half = 0; half < 2; half++) {
        // Coalesced load: 32 rows x 8 float4 chunks (this half) = 4 KB / warp.
        #pragma unroll
        for (int i = 0; i < 8; i++) {
            int f = i * 32 + lane;
            int rr = f >> 3;
            int c = f & 7;
            float4 v = z4[(size_t)(rowBase + rr) * 16 + half * 8 + c];
            zs[warp][rr * 8 + (c ^ (rr & 7))] = v;   // XOR swizzle
        }
        __syncwarp();

        // Lane consumes its own row (conflict-free within each 8-lane phase).
        #pragma unroll
        for (int c = 0; c < 8; c++) {
            float4 zv = zs[warp][lane * 8 + (c ^ (lane & 7))];
            int d = half * 32 + c * 4;
            float4 w0 = wrow[d + 0];
            float4 w1 = wrow[d + 1];
            float4 w2 = wrow[d + 2];
            float4 w3 = wrow[d + 3];
            acc.x = fmaf(zv.x, w0.x, acc.x);
            acc.y = fmaf(zv.x, w0.y, acc.y);
            acc.z = fmaf(zv.x, w0.z, acc.z);
            acc.w = fmaf(zv.x, w0.w, acc.w);
            acc.x = fmaf(zv.y, w1.x, acc.x);
            acc.y = fmaf(zv.y, w1.y, acc.y);
            acc.z = fmaf(zv.y, w1.z, acc.z);
            acc.w = fmaf(zv.y, w1.w, acc.w);
            acc.x = fmaf(zv.z, w2.x, acc.x);
            acc.y = fmaf(zv.z, w2.y, acc.y);
            acc.z = fmaf(zv.z, w2.z, acc.z);
            acc.w = fmaf(zv.z, w2.w, acc.w);
            acc.x = fmaf(zv.w, w3.x, acc.x);
            acc.y = fmaf(zv.w, w3.y, acc.y);
            acc.z = fmaf(zv.w, w3.z, acc.z);
            acc.w = fmaf(zv.w, w3.w, acc.w);
        }
        __syncwarp();
    }

    out[0 * (size_t)B + row] = acc.x;
    out[1 * (size_t)B + row] = acc.y;
    out[2 * (size_t)B + row] = acc.z;
    out[3 * (size_t)B + row] = acc.w;
}

extern "C" void kernel_launch(void* const* d_in, const int* in_sizes, int n_in,
                              void* d_out, int out_size)
{
    // Bind inputs by element count (robust to metadata ordering):
    //   z: B*64 = 268435456, W: 1536, b: 24, pair_idx: B = 4194304
    const void* zp = nullptr; const void* Wp = nullptr;
    const void* bp = nullptr; const void* ip = nullptr;
    int B = 0;
    long long zsz = 0;
    for (int i = 0; i < n_in; i++) {
        if (in_sizes[i] == 1536)      Wp = d_in[i];
        else if (in_sizes[i] == 24)   bp = d_in[i];
        else if (zsz == 0 || in_sizes[i] > zsz) {
            // largest remaining is z; second-largest is pair_idx — handle below
        }
    }
    // Explicit two-pass: find max (z) and the B-sized one (pair_idx).
    int zi = -1, ii = -1;
    for (int i = 0; i < n_in; i++) {
        if (in_sizes[i] == 1536 || in_sizes[i] == 24) continue;
        if (zi < 0 || in_sizes[i] > in_sizes[zi]) zi = i;
    }
    for (int i = 0; i < n_in; i++) {
        if (i == zi || in_sizes[i] == 1536 || in_sizes[i] == 24) continue;
        ii = i;
    }
    zp = d_in[zi];
    ip = d_in[ii];
    B = in_sizes[ii];

    const float4* z4   = (const float4*)zp;
    const float*  Wg   = (const float*)Wp;
    const float*  bg   = (const float*)bp;
    const int*    pidx = (const int*)ip;
    float*        out  = (float*)d_out;

    const int blocks = B / ROWS_PER_BLOCK;
    relation_probe_kernel<<<blocks, 256>>>(z4, Wg, bg, pidx, out, B);
}